// round 16
// baseline (speedup 1.0000x reference)
#include <cuda_runtime.h>
#include <cuda_fp16.h>
#include <math.h>
#include <cstdint>

#define S 2048
#define D 4096
#define H 32
#define HD 128
#define NEGV -1000000000.0f

// Scratch (static device globals -- no allocation allowed)
__device__ __half g_hh[S * D];                 // fp16 hidden [M][K]
__device__ __half g_wth[4][(size_t)D * D];     // fp16 transposed weights [N][K]
__device__ __half g_qh[S * D];                 // fp16 q (GEMM out, roped in place)
__device__ __half g_kh[S * D];                 // fp16 k (GEMM out, roped in place)
__device__ __half g_vh[S * D];                 // fp16 v (GEMM out)
__device__ __half g_aoh[S * D];                // fp16 attention output

// ---------------------------------------------------------------------------
// Helpers
// ---------------------------------------------------------------------------
__device__ __forceinline__ uint32_t smem_u32(const void* p) {
    return (uint32_t)__cvta_generic_to_shared(p);
}
#define MBAR_INIT(addr, cnt) \
    asm volatile("mbarrier.init.shared.b64 [%0], %1;" :: "r"(addr), "r"(cnt) : "memory")
#define MBAR_EXPECT_TX(addr, bytes) \
    asm volatile("mbarrier.arrive.expect_tx.shared.b64 _, [%0], %1;" \
                 :: "r"(addr), "r"(bytes) : "memory")
#define MBAR_ARRIVE(addr) \
    asm volatile("mbarrier.arrive.shared.b64 _, [%0];" :: "r"(addr) : "memory")
__device__ __forceinline__ void mbar_wait(uint32_t addr, uint32_t parity) {
    asm volatile(
        "{\n\t.reg .pred P;\n\t"
        "W%=:\n\t"
        "mbarrier.try_wait.parity.acquire.cta.shared::cta.b64 P, [%0], %1, 0x989680;\n\t"
        "@!P bra W%=;\n\t}"
        :: "r"(addr), "r"(parity) : "memory");
}
#define BULK_LD(dst, src, bytes, mbar) \
    asm volatile("cp.async.bulk.shared::cluster.global.mbarrier::complete_tx::bytes " \
                 "[%0], [%1], %2, [%3];" \
                 :: "r"(dst), "l"(src), "r"(bytes), "r"(mbar) : "memory")

#define MMA_F16(c0, c1, c2, c3, a0, a1, a2, a3, b0, b1) \
    asm volatile( \
        "mma.sync.aligned.m16n8k16.row.col.f32.f16.f16.f32 " \
        "{%0,%1,%2,%3}, {%4,%5,%6,%7}, {%8,%9}, {%0,%1,%2,%3};" \
        : "+f"(c0), "+f"(c1), "+f"(c2), "+f"(c3) \
        : "r"(a0), "r"(a1), "r"(a2), "r"(a3), "r"(b0), "r"(b1))

#define LDSM_X4(r0, r1, r2, r3, addr) \
    asm volatile("ldmatrix.sync.aligned.m8n8.x4.shared.b16 {%0,%1,%2,%3}, [%4];" \
                 : "=r"(r0), "=r"(r1), "=r"(r2), "=r"(r3) : "r"(addr))
#define LDSM_X4_T(r0, r1, r2, r3, addr) \
    asm volatile("ldmatrix.sync.aligned.m8n8.x4.trans.shared.b16 {%0,%1,%2,%3}, [%4];" \
                 : "=r"(r0), "=r"(r1), "=r"(r2), "=r"(r3) : "r"(addr))

// ---------------------------------------------------------------------------
// Fused pre-pass: z=0 converts hidden (4096 blocks active), z=1..4 transpose
// weight z-1 to fp16 [N][K].
// ---------------------------------------------------------------------------
__global__ __launch_bounds__(256) void prep_kernel(
    const float* __restrict__ hidden,
    const float* __restrict__ w0, const float* __restrict__ w1,
    const float* __restrict__ w2, const float* __restrict__ w3,
    __half* __restrict__ hh, __half* __restrict__ wth)
{
    const int z = blockIdx.z;
    if (z == 0) {
        if (blockIdx.x >= (S * D) / (256 * 8)) return;
        size_t i = ((size_t)blockIdx.x * 256 + threadIdx.x) * 8;
        float4 v0 = *(const float4*)(hidden + i);
        float4 v1 = *(const float4*)(hidden + i + 4);
        uint4 p;
        __half2 h;
        h = __floats2half2_rn(v0.x, v0.y); p.x = *(uint32_t*)&h;
        h = __floats2half2_rn(v0.z, v0.w); p.y = *(uint32_t*)&h;
        h = __floats2half2_rn(v1.x, v1.y); p.z = *(uint32_t*)&h;
        h = __floats2half2_rn(v1.z, v1.w); p.w = *(uint32_t*)&h;
        *(uint4*)(hh + i) = p;
        return;
    }
    const float* in = (z == 1) ? w0 : (z == 2) ? w1 : (z == 3) ? w2 : w3;
    __half* out = wth + (size_t)(z - 1) * D * D;
    __shared__ float t[32][33];
    const int tx = threadIdx.x & 31, ty = threadIdx.x >> 5;
    const int bn = (blockIdx.x & 127) * 32;
    const int bk = (blockIdx.x >> 7) * 32;
#pragma unroll
    for (int i = 0; i < 32; i += 8)
        t[ty + i][tx] = in[(size_t)(bk + ty + i) * D + bn + tx];
    __syncthreads();
#pragma unroll
    for (int i = 0; i < 32; i += 8)
        out[(size_t)(bn + ty + i) * D + bk + tx] = __float2half(t[tx][ty + i]);
}

// ---------------------------------------------------------------------------
// fp16 mma.sync GEMM (unchanged, measured best): CTA 128x128, 8 warps 64x32,
// ldmatrix, 3-stage bulk ring, 2 CTAs/SM. nmat folds weight idx into grid.x.
// ---------------------------------------------------------------------------
#define GBM 128
#define GBN 128
#define GBK 64
#define KS_H 72
#define NSTAGE 3
#define STAGE_B (128 * KS_H * 2)
#define SM_MB 0
#define SM_A  128
#define SM_B  (SM_A + NSTAGE * STAGE_B)
#define GEMM_SMEM (SM_B + NSTAGE * STAGE_B)          // 110720 B
#define TILE_TX (GBM * GBK * 2 + GBK * GBN * 2)      // 32768 B

template <int OUT_HALF>
__global__ __launch_bounds__(256, 2) void hgemm_kernel(
    const __half* __restrict__ A, const __half* __restrict__ Wt,
    size_t wstride, int nmat,
    void* __restrict__ C0v, void* __restrict__ C1v, void* __restrict__ C2v)
{
    const int zi  = blockIdx.x % nmat;
    const int bxn = blockIdx.x / nmat;
    const __half* B = Wt + (size_t)zi * wstride;
    void* Cv = (zi == 0) ? C0v : (zi == 1) ? C1v : C2v;

    extern __shared__ float sm[];
    const uint32_t smb = smem_u32(sm);

    const int tid  = threadIdx.x;
    const int warp = tid >> 5;
    const int lane = tid & 31;
    const int lg   = lane >> 2;
    const int lt   = lane & 3;
    const int wm   = warp >> 2;
    const int wn   = warp & 3;
    const int bm   = blockIdx.y * GBM;
    const int bn   = bxn * GBN;

    if (tid == 0) {
        MBAR_INIT(smb + SM_MB + 0,  1);
        MBAR_INIT(smb + SM_MB + 8,  1);
        MBAR_INIT(smb + SM_MB + 16, 1);
    }
    __syncthreads();

    auto issue = [&](int kc, int stg) {
        if (tid == 0)
            MBAR_EXPECT_TX(smb + SM_MB + stg * 8, (uint32_t)TILE_TX);
        if (lane == 0) {
            const uint32_t mb = smb + SM_MB + stg * 8;
            const __half* Ap = A + (size_t)bm * D + kc * GBK;
            uint32_t a_dst = smb + SM_A + stg * STAGE_B + (warp * 16) * (KS_H * 2);
#pragma unroll
            for (int r = 0; r < 16; r++)
                BULK_LD(a_dst + r * (KS_H * 2),
                        Ap + (size_t)(warp * 16 + r) * D, 128u, mb);
            const __half* Bp = B + (size_t)bn * D + kc * GBK;
            uint32_t b_dst = smb + SM_B + stg * STAGE_B + (warp * 16) * (KS_H * 2);
#pragma unroll
            for (int r = 0; r < 16; r++)
                BULK_LD(b_dst + r * (KS_H * 2),
                        Bp + (size_t)(warp * 16 + r) * D, 128u, mb);
        }
    };

    float c[4][4][4];
#pragma unroll
    for (int mi = 0; mi < 4; mi++)
#pragma unroll
        for (int ni = 0; ni < 4; ni++)
#pragma unroll
            for (int r = 0; r < 4; r++) c[mi][ni][r] = 0.0f;

    const uint32_t a_row_off =
        (uint32_t)(wm * 64 + (lane & 15)) * (KS_H * 2) + ((lane >> 4) << 3) * 2;
    const uint32_t b_row_off =
        (uint32_t)(wn * 32 + (lane & 7) + (((lane >> 4) & 1) << 3)) * (KS_H * 2)
        + (((lane >> 3) & 1) << 3) * 2;

    const int nk = D / GBK;
    issue(0, 0);
    issue(1, 1);
    issue(2, 2);

    for (int kc = 0; kc < nk; kc++) {
        const int stg = kc % NSTAGE;
        mbar_wait(smb + SM_MB + stg * 8, (uint32_t)((kc / NSTAGE) & 1));

        const uint32_t aBase = smb + SM_A + stg * STAGE_B + a_row_off;
        const uint32_t bBase = smb + SM_B + stg * STAGE_B + b_row_off;
#pragma unroll
        for (int ks = 0; ks < GBK / 16; ks++) {
            const uint32_t kb = ks * 32;
            uint32_t af[4][4];
#pragma unroll
            for (int mi = 0; mi < 4; mi++)
                LDSM_X4(af[mi][0], af[mi][1], af[mi][2], af[mi][3],
                        aBase + mi * 16 * (KS_H * 2) + kb);
            uint32_t bf[4][2];
#pragma unroll
            for (int nj = 0; nj < 2; nj++)
                LDSM_X4(bf[nj * 2][0], bf[nj * 2][1],
                        bf[nj * 2 + 1][0], bf[nj * 2 + 1][1],
                        bBase + nj * 16 * (KS_H * 2) + kb);
#pragma unroll
            for (int mi = 0; mi < 4; mi++)
#pragma unroll
                for (int ni = 0; ni < 4; ni++)
                    MMA_F16(c[mi][ni][0], c[mi][ni][1], c[mi][ni][2], c[mi][ni][3],
                            af[mi][0], af[mi][1], af[mi][2], af[mi][3],
                            bf[ni][0], bf[ni][1]);
        }
        __syncthreads();
        if (kc + NSTAGE < nk)
            issue(kc + NSTAGE, stg);
    }

#pragma unroll
    for (int mi = 0; mi < 4; mi++) {
        int r0 = bm + wm * 64 + mi * 16 + lg;
#pragma unroll
        for (int ni = 0; ni < 4; ni++) {
            int col = bn + wn * 32 + ni * 8 + lt * 2;
            if (OUT_HALF) {
                __half* C = (__half*)Cv;
                *(__half2*)(C + (size_t)r0 * D + col) =
                    __floats2half2_rn(c[mi][ni][0], c[mi][ni][1]);
                *(__half2*)(C + (size_t)(r0 + 8) * D + col) =
                    __floats2half2_rn(c[mi][ni][2], c[mi][ni][3]);
            } else {
                float* C = (float*)Cv;
                *(float2*)(C + (size_t)r0 * D + col) =
                    make_float2(c[mi][ni][0], c[mi][ni][1]);
                *(float2*)(C + (size_t)(r0 + 8) * D + col) =
                    make_float2(c[mi][ni][2], c[mi][ni][3]);
            }
        }
    }
}

// ---------------------------------------------------------------------------
// In-place fp16 RoPE on q/k (grid.y selects). fp32 math, half2 I/O.
// ---------------------------------------------------------------------------
__global__ __launch_bounds__(256) void rope_h_kernel(
    __half* __restrict__ xq, __half* __restrict__ xk,
    const float* __restrict__ cosp, const float* __restrict__ sinp)
{
    __half* x = blockIdx.y ? xk : xq;
    int idx = blockIdx.x * 256 + threadIdx.x;
    int s = idx >> 10;
    int i = (idx & 1023) * 2;
    size_t base = (size_t)s * D;

    float2 lo = __half22float2(*(__half2*)(x + base + i));
    float2 hi = __half22float2(*(__half2*)(x + base + i + 2048));
    float2 c1 = *(const float2*)(cosp + base + i);
    float2 s1 = *(const float2*)(sinp + base + i);
    float2 c2 = *(const float2*)(cosp + base + i + 2048);
    float2 s2 = *(const float2*)(sinp + base + i + 2048);
    float2 nlo, nhi;
    nlo.x = lo.x * c1.x - hi.x * s1.x;
    nlo.y = lo.y * c1.y - hi.y * s1.y;
    nhi.x = hi.x * c2.x + lo.x * s2.x;
    nhi.y = hi.y * c2.y + lo.y * s2.y;
    *(__half2*)(x + base + i)        = __floats2half2_rn(nlo.x, nlo.y);
    *(__half2*)(x + base + i + 2048) = __floats2half2_rn(nhi.x, nhi.y);
}

// ---------------------------------------------------------------------------
// Flash attention, fp16 mma, 3-stage K/V bulk ring with full/empty mbarriers
// (NO CTA-wide barrier in the loop -- warps pipeline independently).
// amask read directly from global (prefetched before the full-wait).
// CTA = 128 q x 1 head, 8 warps; warp owns 16 q rows end-to-end.
// ---------------------------------------------------------------------------
#define AQB 128
#define AKC 64
#define KV_STRIDE 272
#define KV_U 68
#define PH_STRIDE 144
#define PH_U 36
#define ANS 3                          // attention stage count
#define A_FULL 0                       // 3 x 8 B
#define A_EMPTY 24                     // 3 x 8 B
#define A_K  128
#define K_STG (AKC * KV_STRIDE)        // 17408
#define A_V  (A_K + ANS * K_STG)       // 52352
#define A_PH (A_V + ANS * K_STG)       // 104576
#define ATTN_SMEM (A_PH + AQB * PH_STRIDE)   // 123008
#define W_TX (16 * 256)                // per-warp tx bytes per stage

__global__ __launch_bounds__(256, 1) void attn_kernel(
    const __half* __restrict__ Q, const __half* __restrict__ K,
    const __half* __restrict__ V, const float* __restrict__ amask,
    __half* __restrict__ O)
{
    extern __shared__ char smc[];
    const uint32_t smb = smem_u32(smc);

    const int tid  = threadIdx.x;
    const int w    = tid >> 5;
    const int lane = tid & 31;
    const int lg   = lane >> 2;
    const int lt   = lane & 3;
    const int qb   = blockIdx.x * AQB;
    const int h0   = blockIdx.y * HD;
    const int rl0  = w * 16 + lg;
    const int r0   = qb + rl0;
    const int r1   = r0 + 8;

    if (tid == 0) {
#pragma unroll
        for (int s = 0; s < ANS; s++) {
            MBAR_INIT(smb + A_FULL + s * 8, 8);    // 8 producer warps
            MBAR_INIT(smb + A_EMPTY + s * 8, 8);   // 8 consumer warps
        }
    }
    __syncthreads();

    // per-warp producer: lane0 expects its tx and bulk-issues 8 K + 8 V rows
    auto issue = [&](int kc, int stg) {
        if (lane == 0) {
            const uint32_t mb = smb + A_FULL + stg * 8;
            MBAR_EXPECT_TX(mb, (uint32_t)W_TX);
            uint32_t kdst = smb + A_K + stg * K_STG + (w * 8) * KV_STRIDE;
            uint32_t vdst = smb + A_V + stg * K_STG + (w * 8) * KV_STRIDE;
#pragma unroll
            for (int r = 0; r < 8; r++) {
                BULK_LD(kdst + r * KV_STRIDE,
                        K + (size_t)(kc + w * 8 + r) * D + h0, 256u, mb);
                BULK_LD(vdst + r * KV_STRIDE,
                        V + (size_t)(kc + w * 8 + r) * D + h0, 256u, mb);
            }
        }
    };

    // Q fragments (fp16): 8 k16 steps x 4 regs
    uint32_t qf[8][4];
    {
        const __half* Qp0 = Q + (size_t)r0 * D + h0;
        const __half* Qp1 = Qp0 + 8 * (size_t)D;
#pragma unroll
        for (int ks = 0; ks < 8; ks++) {
            qf[ks][0] = *(const uint32_t*)(Qp0 + ks * 16 + 2 * lt);
            qf[ks][1] = *(const uint32_t*)(Qp1 + ks * 16 + 2 * lt);
            qf[ks][2] = *(const uint32_t*)(Qp0 + ks * 16 + 8 + 2 * lt);
            qf[ks][3] = *(const uint32_t*)(Qp1 + ks * 16 + 8 + 2 * lt);
        }
    }

    float o[16][4];
#pragma unroll
    for (int ni = 0; ni < 16; ni++)
#pragma unroll
        for (int r = 0; r < 4; r++) o[ni][r] = 0.0f;
    float m0 = -INFINITY, m1 = -INFINITY, l0 = 0.0f, l1 = 0.0f;

    const int kc0 = (qb == S - AQB) ? 0 : qb;

    // prologue: fill up to ANS stages
    {
        int ni = 0;
        for (int kc = kc0; kc < S && ni < ANS; kc += AKC, ni++)
            issue(kc, ni);
    }

    uint32_t* Phb = (uint32_t*)(smc + A_PH);
    const uint32_t v_lane_off =
        (uint32_t)((lane & 7) + (((lane >> 3) & 1) << 3)) * KV_STRIDE
        + (((lane >> 4) & 1) << 3) * 2;
    const float* am0p = amask + (size_t)r0 * S;
    const float* am1p = amask + (size_t)r1 * S;

    int idx = 0;
    for (int kc = kc0; kc < S; kc += AKC, idx++) {
        const int stg = idx % ANS;
        const uint32_t fpar = (uint32_t)((idx / ANS) & 1);

        // prefetch amask for this chunk (independent of stage readiness)
        float2 am0[8], am1[8];
#pragma unroll
        for (int ni = 0; ni < 8; ni++) {
            int col = kc + ni * 8 + lt * 2;
            am0[ni] = *(const float2*)(am0p + col);
            am1[ni] = *(const float2*)(am1p + col);
        }

        mbar_wait(smb + A_FULL + stg * 8, fpar);

        const uint32_t* Khb = (const uint32_t*)(smc + A_K + stg * K_STG);
        const uint32_t  vBase = smb + A_V + stg * K_STG + v_lane_off;

        // S = Q @ K^T
        float s[8][4];
#pragma unroll
        for (int ni = 0; ni < 8; ni++)
#pragma unroll
            for (int r = 0; r < 4; r++) s[ni][r] = 0.0f;
#pragma unroll
        for (int ks = 0; ks < 8; ks++) {
#pragma unroll
            for (int ni = 0; ni < 8; ni++) {
                uint32_t b0 = Khb[(ni * 8 + lg) * KV_U + ks * 8 + lt];
                uint32_t b1 = Khb[(ni * 8 + lg) * KV_U + ks * 8 + 4 + lt];
                MMA_F16(s[ni][0], s[ni][1], s[ni][2], s[ni][3],
                        qf[ks][0], qf[ks][1], qf[ks][2], qf[ks][3], b0, b1);
            }
        }

        // scale + amask + causal NEG, row max
        float mx0 = -INFINITY, mx1 = -INFINITY;
#pragma unroll
        for (int ni = 0; ni < 8; ni++) {
            int col = ni * 8 + lt * 2;
            int key = kc + col;
            float v0 = s[ni][0] * 0.015625f + am0[ni].x;
            float v1 = s[ni][1] * 0.015625f + am0[ni].y;
            float v2 = s[ni][2] * 0.015625f + am1[ni].x;
            float v3 = s[ni][3] * 0.015625f + am1[ni].y;
            if (key     <= r0) v0 += NEGV;
            if (key + 1 <= r0) v1 += NEGV;
            if (key     <= r1) v2 += NEGV;
            if (key + 1 <= r1) v3 += NEGV;
            s[ni][0] = v0; s[ni][1] = v1; s[ni][2] = v2; s[ni][3] = v3;
            mx0 = fmaxf(mx0, fmaxf(v0, v1));
            mx1 = fmaxf(mx1, fmaxf(v2, v3));
        }
        mx0 = fmaxf(mx0, __shfl_xor_sync(0xffffffffu, mx0, 1));
        mx0 = fmaxf(mx0, __shfl_xor_sync(0xffffffffu, mx0, 2));
        mx1 = fmaxf(mx1, __shfl_xor_sync(0xffffffffu, mx1, 1));
        mx1 = fmaxf(mx1, __shfl_xor_sync(0xffffffffu, mx1, 2));

        float nm0 = fmaxf(m0, mx0), nm1 = fmaxf(m1, mx1);
        float corr0 = __expf(m0 - nm0), corr1 = __expf(m1 - nm1);
        float ls0 = 0.0f, ls1 = 0.0f;
#pragma unroll
        for (int ni = 0; ni < 8; ni++) {
            float p0 = __expf(s[ni][0] - nm0);
            float p1 = __expf(s[ni][1] - nm0);
            float p2 = __expf(s[ni][2] - nm1);
            float p3 = __expf(s[ni][3] - nm1);
            ls0 += p0 + p1;
            ls1 += p2 + p3;
            __half2 h01 = __floats2half2_rn(p0, p1);
            __half2 h23 = __floats2half2_rn(p2, p3);
            Phb[rl0 * PH_U + ni * 4 + lt]       = *(uint32_t*)&h01;
            Phb[(rl0 + 8) * PH_U + ni * 4 + lt] = *(uint32_t*)&h23;
        }
        ls0 += __shfl_xor_sync(0xffffffffu, ls0, 1);
        ls0 += __shfl_xor_sync(0xffffffffu, ls0, 2);
        ls1 += __shfl_xor_sync(0xffffffffu, ls1, 1);
        ls1 += __shfl_xor_sync(0xffffffffu, ls1, 2);
        l0 = l0 * corr0 + ls0;
        l1 = l1 * corr1 + ls1;
        m0 = nm0; m1 = nm1;
#pragma unroll
        for (int ni = 0; ni < 16; ni++) {
            o[ni][0] *= corr0; o[ni][1] *= corr0;
            o[ni][2] *= corr1; o[ni][3] *= corr1;
        }
        __syncwarp();

        // O += P @ V
#pragma unroll
        for (int ks = 0; ks < 4; ks++) {
            uint32_t a0 = Phb[rl0 * PH_U + ks * 8 + lt];
            uint32_t a1 = Phb[(rl0 + 8) * PH_U + ks * 8 + lt];
            uint32_t a2 = Phb[rl0 * PH_U + ks * 8 + 4 + lt];
            uint32_t a3 = Phb[(rl0 + 8) * PH_U + ks * 8 + 4 + lt];
#pragma unroll
            for (int nj = 0; nj < 8; nj++) {
                uint32_t b0, b1, b2, b3;
                LDSM_X4_T(b0, b1, b2, b3,
                          vBase + (ks * 16) * KV_STRIDE + nj * 32);
                MMA_F16(o[nj * 2][0], o[nj * 2][1], o[nj * 2][2], o[nj * 2][3],
                        a0, a1, a2, a3, b0, b1);
                MMA_F16(o[nj * 2 + 1][0], o[nj * 2 + 1][1],
                        o[nj * 2 + 1][2], o[nj * 2 + 1][3],
                        a0, a1, a2, a3, b2, b3);
            }
        }

        // this warp is done reading stage stg
        __syncwarp();
        if (lane == 0)
            MBAR_ARRIVE(smb + A_EMPTY + stg * 8);

        // refill stage stg with chunk idx+ANS (wait until all warps released it)
        if (kc + ANS * AKC < S) {
            if (lane == 0)
                mbar_wait(smb + A_EMPTY + stg * 8, fpar);
            issue(kc + ANS * AKC, stg);
        }
    }

    // epilogue: /l, fp16 out
    float inv0 = 1.0f / l0, inv1 = 1.0f / l1;
#pragma unroll
    for (int ni = 0; ni < 16; ni++) {
        int col = ni * 8 + lt * 2;
        __half2 w0 = __floats2half2_rn(o[ni][0] * inv0, o[ni][1] * inv0);
        __half2 w1 = __floats2half2_rn(o[ni][2] * inv1, o[ni][3] * inv1);
        *(__half2*)(O + (size_t)r0 * D + h0 + col) = w0;
        *(__half2*)(O + (size_t)r1 * D + h0 + col) = w1;
    }
}

// ---------------------------------------------------------------------------
extern "C" void kernel_launch(void* const* d_in, const int* in_sizes, int n_in,
                              void* d_out, int out_size)
{
    const float* hidden = (const float*)d_in[0];
    const float* amask  = (const float*)d_in[1];
    const float* cosp   = (const float*)d_in[2];
    const float* sinp   = (const float*)d_in[3];
    const float* wq     = (const float*)d_in[4];
    const float* wk     = (const float*)d_in[5];
    const float* wv     = (const float*)d_in[6];
    const float* wo     = (const float*)d_in[7];
    float* out = (float*)d_out;

    __half *hh, *wth, *qh, *kh, *vh, *aoh;
    cudaGetSymbolAddress((void**)&hh,  g_hh);
    cudaGetSymbolAddress((void**)&wth, g_wth);
    cudaGetSymbolAddress((void**)&qh,  g_qh);
    cudaGetSymbolAddress((void**)&kh,  g_kh);
    cudaGetSymbolAddress((void**)&vh,  g_vh);
    cudaGetSymbolAddress((void**)&aoh, g_aoh);

    cudaFuncSetAttribute(attn_kernel,
                         cudaFuncAttributeMaxDynamicSharedMemorySize, ATTN_SMEM);
    cudaFuncSetAttribute(hgemm_kernel<1>,
                         cudaFuncAttributeMaxDynamicSharedMemorySize, GEMM_SMEM);
    cudaFuncSetAttribute(hgemm_kernel<0>,
                         cudaFuncAttributeMaxDynamicSharedMemorySize, GEMM_SMEM);

    prep_kernel<<<dim3(16384, 1, 5), 256>>>(hidden, wq, wk, wv, wo, hh, wth);

    hgemm_kernel<1><<<dim3(3 * (D / GBN), S / GBM), 256, GEMM_SMEM>>>(
        hh, wth, (size_t)D * D, 3, qh, kh, vh);

    rope_h_kernel<<<dim3((S * D / 4) / 256, 2), 256>>>(qh, kh, cosp, sinp);

    attn_kernel<<<dim3(S / AQB, H), 256, ATTN_SMEM>>>(qh, kh, vh, amask, aoh);

    hgemm_kernel<0><<<dim3(D / GBN, S / GBM), 256, GEMM_SMEM>>>(
        aoh, wth + 3 * (size_t)D * D, 0, 1, out, out, out);
}

// round 17
// speedup vs baseline: 1.0122x; 1.0122x over previous
#include <cuda_runtime.h>
#include <cuda_fp16.h>
#include <math.h>
#include <cstdint>

#define S 2048
#define D 4096
#define H 32
#define HD 128
#define NEGV -1000000000.0f

// Scratch (static device globals -- no allocation allowed)
__device__ __half g_hh[S * D];                 // fp16 hidden [M][K]
__device__ __half g_wth[4][(size_t)D * D];     // fp16 transposed weights [N][K]
__device__ __half g_qh[S * D];                 // fp16 q (GEMM out, roped in place)
__device__ __half g_kh[S * D];                 // fp16 k (GEMM out, roped in place)
__device__ __half g_vh[S * D];                 // fp16 v (GEMM out)
__device__ __half g_aoh[S * D];                // fp16 attention output

// ---------------------------------------------------------------------------
// Helpers
// ---------------------------------------------------------------------------
__device__ __forceinline__ uint32_t smem_u32(const void* p) {
    return (uint32_t)__cvta_generic_to_shared(p);
}
#define MBAR_INIT(addr, cnt) \
    asm volatile("mbarrier.init.shared.b64 [%0], %1;" :: "r"(addr), "r"(cnt) : "memory")
#define MBAR_EXPECT_TX(addr, bytes) \
    asm volatile("mbarrier.arrive.expect_tx.shared.b64 _, [%0], %1;" \
                 :: "r"(addr), "r"(bytes) : "memory")
#define MBAR_ARRIVE(addr) \
    asm volatile("mbarrier.arrive.shared.b64 _, [%0];" :: "r"(addr) : "memory")
__device__ __forceinline__ void mbar_wait(uint32_t addr, uint32_t parity) {
    asm volatile(
        "{\n\t.reg .pred P;\n\t"
        "W%=:\n\t"
        "mbarrier.try_wait.parity.acquire.cta.shared::cta.b64 P, [%0], %1, 0x989680;\n\t"
        "@!P bra W%=;\n\t}"
        :: "r"(addr), "r"(parity) : "memory");
}
#define BULK_LD(dst, src, bytes, mbar) \
    asm volatile("cp.async.bulk.shared::cluster.global.mbarrier::complete_tx::bytes " \
                 "[%0], [%1], %2, [%3];" \
                 :: "r"(dst), "l"(src), "r"(bytes), "r"(mbar) : "memory")

#define MMA_F16(c0, c1, c2, c3, a0, a1, a2, a3, b0, b1) \
    asm volatile( \
        "mma.sync.aligned.m16n8k16.row.col.f32.f16.f16.f32 " \
        "{%0,%1,%2,%3}, {%4,%5,%6,%7}, {%8,%9}, {%0,%1,%2,%3};" \
        : "+f"(c0), "+f"(c1), "+f"(c2), "+f"(c3) \
        : "r"(a0), "r"(a1), "r"(a2), "r"(a3), "r"(b0), "r"(b1))

#define LDSM_X4(r0, r1, r2, r3, addr) \
    asm volatile("ldmatrix.sync.aligned.m8n8.x4.shared.b16 {%0,%1,%2,%3}, [%4];" \
                 : "=r"(r0), "=r"(r1), "=r"(r2), "=r"(r3) : "r"(addr))
#define LDSM_X4_T(r0, r1, r2, r3, addr) \
    asm volatile("ldmatrix.sync.aligned.m8n8.x4.trans.shared.b16 {%0,%1,%2,%3}, [%4];" \
                 : "=r"(r0), "=r"(r1), "=r"(r2), "=r"(r3) : "r"(addr))

// ---------------------------------------------------------------------------
// Fused pre-pass: z=0 converts hidden (4096 blocks active), z=1..4 transpose
// weight z-1 to fp16 [N][K].
// ---------------------------------------------------------------------------
__global__ __launch_bounds__(256) void prep_kernel(
    const float* __restrict__ hidden,
    const float* __restrict__ w0, const float* __restrict__ w1,
    const float* __restrict__ w2, const float* __restrict__ w3,
    __half* __restrict__ hh, __half* __restrict__ wth)
{
    const int z = blockIdx.z;
    if (z == 0) {
        if (blockIdx.x >= (S * D) / (256 * 8)) return;
        size_t i = ((size_t)blockIdx.x * 256 + threadIdx.x) * 8;
        float4 v0 = *(const float4*)(hidden + i);
        float4 v1 = *(const float4*)(hidden + i + 4);
        uint4 p;
        __half2 h;
        h = __floats2half2_rn(v0.x, v0.y); p.x = *(uint32_t*)&h;
        h = __floats2half2_rn(v0.z, v0.w); p.y = *(uint32_t*)&h;
        h = __floats2half2_rn(v1.x, v1.y); p.z = *(uint32_t*)&h;
        h = __floats2half2_rn(v1.z, v1.w); p.w = *(uint32_t*)&h;
        *(uint4*)(hh + i) = p;
        return;
    }
    const float* in = (z == 1) ? w0 : (z == 2) ? w1 : (z == 3) ? w2 : w3;
    __half* out = wth + (size_t)(z - 1) * D * D;
    __shared__ float t[32][33];
    const int tx = threadIdx.x & 31, ty = threadIdx.x >> 5;
    const int bn = (blockIdx.x & 127) * 32;
    const int bk = (blockIdx.x >> 7) * 32;
#pragma unroll
    for (int i = 0; i < 32; i += 8)
        t[ty + i][tx] = in[(size_t)(bk + ty + i) * D + bn + tx];
    __syncthreads();
#pragma unroll
    for (int i = 0; i < 32; i += 8)
        out[(size_t)(bn + ty + i) * D + bk + tx] = __float2half(t[tx][ty + i]);
}

// ---------------------------------------------------------------------------
// fp16 mma.sync GEMM (unchanged, measured best): CTA 128x128, 8 warps 64x32,
// ldmatrix, 3-stage bulk ring, 2 CTAs/SM. nmat folds weight idx into grid.x.
// ---------------------------------------------------------------------------
#define GBM 128
#define GBN 128
#define GBK 64
#define KS_H 72
#define NSTAGE 3
#define STAGE_B (128 * KS_H * 2)
#define SM_MB 0
#define SM_A  128
#define SM_B  (SM_A + NSTAGE * STAGE_B)
#define GEMM_SMEM (SM_B + NSTAGE * STAGE_B)          // 110720 B
#define TILE_TX (GBM * GBK * 2 + GBK * GBN * 2)      // 32768 B

template <int OUT_HALF>
__global__ __launch_bounds__(256, 2) void hgemm_kernel(
    const __half* __restrict__ A, const __half* __restrict__ Wt,
    size_t wstride, int nmat,
    void* __restrict__ C0v, void* __restrict__ C1v, void* __restrict__ C2v)
{
    const int zi  = blockIdx.x % nmat;
    const int bxn = blockIdx.x / nmat;
    const __half* B = Wt + (size_t)zi * wstride;
    void* Cv = (zi == 0) ? C0v : (zi == 1) ? C1v : C2v;

    extern __shared__ float sm[];
    const uint32_t smb = smem_u32(sm);

    const int tid  = threadIdx.x;
    const int warp = tid >> 5;
    const int lane = tid & 31;
    const int lg   = lane >> 2;
    const int lt   = lane & 3;
    const int wm   = warp >> 2;
    const int wn   = warp & 3;
    const int bm   = blockIdx.y * GBM;
    const int bn   = bxn * GBN;

    if (tid == 0) {
        MBAR_INIT(smb + SM_MB + 0,  1);
        MBAR_INIT(smb + SM_MB + 8,  1);
        MBAR_INIT(smb + SM_MB + 16, 1);
    }
    __syncthreads();

    auto issue = [&](int kc, int stg) {
        if (tid == 0)
            MBAR_EXPECT_TX(smb + SM_MB + stg * 8, (uint32_t)TILE_TX);
        if (lane == 0) {
            const uint32_t mb = smb + SM_MB + stg * 8;
            const __half* Ap = A + (size_t)bm * D + kc * GBK;
            uint32_t a_dst = smb + SM_A + stg * STAGE_B + (warp * 16) * (KS_H * 2);
#pragma unroll
            for (int r = 0; r < 16; r++)
                BULK_LD(a_dst + r * (KS_H * 2),
                        Ap + (size_t)(warp * 16 + r) * D, 128u, mb);
            const __half* Bp = B + (size_t)bn * D + kc * GBK;
            uint32_t b_dst = smb + SM_B + stg * STAGE_B + (warp * 16) * (KS_H * 2);
#pragma unroll
            for (int r = 0; r < 16; r++)
                BULK_LD(b_dst + r * (KS_H * 2),
                        Bp + (size_t)(warp * 16 + r) * D, 128u, mb);
        }
    };

    float c[4][4][4];
#pragma unroll
    for (int mi = 0; mi < 4; mi++)
#pragma unroll
        for (int ni = 0; ni < 4; ni++)
#pragma unroll
            for (int r = 0; r < 4; r++) c[mi][ni][r] = 0.0f;

    const uint32_t a_row_off =
        (uint32_t)(wm * 64 + (lane & 15)) * (KS_H * 2) + ((lane >> 4) << 3) * 2;
    const uint32_t b_row_off =
        (uint32_t)(wn * 32 + (lane & 7) + (((lane >> 4) & 1) << 3)) * (KS_H * 2)
        + (((lane >> 3) & 1) << 3) * 2;

    const int nk = D / GBK;
    issue(0, 0);
    issue(1, 1);
    issue(2, 2);

    for (int kc = 0; kc < nk; kc++) {
        const int stg = kc % NSTAGE;
        mbar_wait(smb + SM_MB + stg * 8, (uint32_t)((kc / NSTAGE) & 1));

        const uint32_t aBase = smb + SM_A + stg * STAGE_B + a_row_off;
        const uint32_t bBase = smb + SM_B + stg * STAGE_B + b_row_off;
#pragma unroll
        for (int ks = 0; ks < GBK / 16; ks++) {
            const uint32_t kb = ks * 32;
            uint32_t af[4][4];
#pragma unroll
            for (int mi = 0; mi < 4; mi++)
                LDSM_X4(af[mi][0], af[mi][1], af[mi][2], af[mi][3],
                        aBase + mi * 16 * (KS_H * 2) + kb);
            uint32_t bf[4][2];
#pragma unroll
            for (int nj = 0; nj < 2; nj++)
                LDSM_X4(bf[nj * 2][0], bf[nj * 2][1],
                        bf[nj * 2 + 1][0], bf[nj * 2 + 1][1],
                        bBase + nj * 16 * (KS_H * 2) + kb);
#pragma unroll
            for (int mi = 0; mi < 4; mi++)
#pragma unroll
                for (int ni = 0; ni < 4; ni++)
                    MMA_F16(c[mi][ni][0], c[mi][ni][1], c[mi][ni][2], c[mi][ni][3],
                            af[mi][0], af[mi][1], af[mi][2], af[mi][3],
                            bf[ni][0], bf[ni][1]);
        }
        __syncthreads();
        if (kc + NSTAGE < nk)
            issue(kc + NSTAGE, stg);
    }

#pragma unroll
    for (int mi = 0; mi < 4; mi++) {
        int r0 = bm + wm * 64 + mi * 16 + lg;
#pragma unroll
        for (int ni = 0; ni < 4; ni++) {
            int col = bn + wn * 32 + ni * 8 + lt * 2;
            if (OUT_HALF) {
                __half* C = (__half*)Cv;
                *(__half2*)(C + (size_t)r0 * D + col) =
                    __floats2half2_rn(c[mi][ni][0], c[mi][ni][1]);
                *(__half2*)(C + (size_t)(r0 + 8) * D + col) =
                    __floats2half2_rn(c[mi][ni][2], c[mi][ni][3]);
            } else {
                float* C = (float*)Cv;
                *(float2*)(C + (size_t)r0 * D + col) =
                    make_float2(c[mi][ni][0], c[mi][ni][1]);
                *(float2*)(C + (size_t)(r0 + 8) * D + col) =
                    make_float2(c[mi][ni][2], c[mi][ni][3]);
            }
        }
    }
}

// ---------------------------------------------------------------------------
// In-place fp16 RoPE on q/k (grid.y selects). fp32 math, half2 I/O.
// ---------------------------------------------------------------------------
__global__ __launch_bounds__(256) void rope_h_kernel(
    __half* __restrict__ xq, __half* __restrict__ xk,
    const float* __restrict__ cosp, const float* __restrict__ sinp)
{
    __half* x = blockIdx.y ? xk : xq;
    int idx = blockIdx.x * 256 + threadIdx.x;
    int s = idx >> 10;
    int i = (idx & 1023) * 2;
    size_t base = (size_t)s * D;

    float2 lo = __half22float2(*(__half2*)(x + base + i));
    float2 hi = __half22float2(*(__half2*)(x + base + i + 2048));
    float2 c1 = *(const float2*)(cosp + base + i);
    float2 s1 = *(const float2*)(sinp + base + i);
    float2 c2 = *(const float2*)(cosp + base + i + 2048);
    float2 s2 = *(const float2*)(sinp + base + i + 2048);
    float2 nlo, nhi;
    nlo.x = lo.x * c1.x - hi.x * s1.x;
    nlo.y = lo.y * c1.y - hi.y * s1.y;
    nhi.x = hi.x * c2.x + lo.x * s2.x;
    nhi.y = hi.y * c2.y + lo.y * s2.y;
    *(__half2*)(x + base + i)        = __floats2half2_rn(nlo.x, nlo.y);
    *(__half2*)(x + base + i + 2048) = __floats2half2_rn(nhi.x, nhi.y);
}

// ---------------------------------------------------------------------------
// Flash attention, fp16 mma, 3-stage K/V bulk ring with full/empty mbarriers,
// REGISTER-PASSED P (QK C-fragment == PV A-fragment layout; no P smem).
// CTA = 128 q x 1 head, 8 warps; warp owns 16 q rows end-to-end.
// amask read directly from global (prefetched before the full-wait).
// ---------------------------------------------------------------------------
#define AQB 128
#define AKC 64
#define KV_STRIDE 272
#define KV_U 68
#define ANS 3
#define A_FULL 0
#define A_EMPTY 24
#define A_K  128
#define K_STG (AKC * KV_STRIDE)        // 17408
#define A_V  (A_K + ANS * K_STG)       // 52352
#define ATTN_SMEM (A_V + ANS * K_STG)  // 104576
#define W_TX (16 * 256)

__global__ __launch_bounds__(256, 1) void attn_kernel(
    const __half* __restrict__ Q, const __half* __restrict__ K,
    const __half* __restrict__ V, const float* __restrict__ amask,
    __half* __restrict__ O)
{
    extern __shared__ char smc[];
    const uint32_t smb = smem_u32(smc);

    const int tid  = threadIdx.x;
    const int w    = tid >> 5;
    const int lane = tid & 31;
    const int lg   = lane >> 2;
    const int lt   = lane & 3;
    const int qb   = blockIdx.x * AQB;
    const int h0   = blockIdx.y * HD;
    const int rl0  = w * 16 + lg;
    const int r0   = qb + rl0;
    const int r1   = r0 + 8;

    if (tid == 0) {
#pragma unroll
        for (int s = 0; s < ANS; s++) {
            MBAR_INIT(smb + A_FULL + s * 8, 8);
            MBAR_INIT(smb + A_EMPTY + s * 8, 8);
        }
    }
    __syncthreads();

    auto issue = [&](int kc, int stg) {
        if (lane == 0) {
            const uint32_t mb = smb + A_FULL + stg * 8;
            MBAR_EXPECT_TX(mb, (uint32_t)W_TX);
            uint32_t kdst = smb + A_K + stg * K_STG + (w * 8) * KV_STRIDE;
            uint32_t vdst = smb + A_V + stg * K_STG + (w * 8) * KV_STRIDE;
#pragma unroll
            for (int r = 0; r < 8; r++) {
                BULK_LD(kdst + r * KV_STRIDE,
                        K + (size_t)(kc + w * 8 + r) * D + h0, 256u, mb);
                BULK_LD(vdst + r * KV_STRIDE,
                        V + (size_t)(kc + w * 8 + r) * D + h0, 256u, mb);
            }
        }
    };

    uint32_t qf[8][4];
    {
        const __half* Qp0 = Q + (size_t)r0 * D + h0;
        const __half* Qp1 = Qp0 + 8 * (size_t)D;
#pragma unroll
        for (int ks = 0; ks < 8; ks++) {
            qf[ks][0] = *(const uint32_t*)(Qp0 + ks * 16 + 2 * lt);
            qf[ks][1] = *(const uint32_t*)(Qp1 + ks * 16 + 2 * lt);
            qf[ks][2] = *(const uint32_t*)(Qp0 + ks * 16 + 8 + 2 * lt);
            qf[ks][3] = *(const uint32_t*)(Qp1 + ks * 16 + 8 + 2 * lt);
        }
    }

    float o[16][4];
#pragma unroll
    for (int ni = 0; ni < 16; ni++)
#pragma unroll
        for (int r = 0; r < 4; r++) o[ni][r] = 0.0f;
    float m0 = -INFINITY, m1 = -INFINITY, l0 = 0.0f, l1 = 0.0f;

    const int kc0 = (qb == S - AQB) ? 0 : qb;

    {
        int ni = 0;
        for (int kc = kc0; kc < S && ni < ANS; kc += AKC, ni++)
            issue(kc, ni);
    }

    const uint32_t v_lane_off =
        (uint32_t)((lane & 7) + (((lane >> 3) & 1) << 3)) * KV_STRIDE
        + (((lane >> 4) & 1) << 3) * 2;
    const float* am0p = amask + (size_t)r0 * S;
    const float* am1p = amask + (size_t)r1 * S;

    int idx = 0;
    for (int kc = kc0; kc < S; kc += AKC, idx++) {
        const int stg = idx % ANS;
        const uint32_t fpar = (uint32_t)((idx / ANS) & 1);

        // prefetch amask (independent of stage readiness)
        float2 am0[8], am1[8];
#pragma unroll
        for (int ni = 0; ni < 8; ni++) {
            int col = kc + ni * 8 + lt * 2;
            am0[ni] = *(const float2*)(am0p + col);
            am1[ni] = *(const float2*)(am1p + col);
        }

        mbar_wait(smb + A_FULL + stg * 8, fpar);

        const uint32_t* Khb = (const uint32_t*)(smc + A_K + stg * K_STG);
        const uint32_t  vBase = smb + A_V + stg * K_STG + v_lane_off;

        // S = Q @ K^T
        float s[8][4];
#pragma unroll
        for (int ni = 0; ni < 8; ni++)
#pragma unroll
            for (int r = 0; r < 4; r++) s[ni][r] = 0.0f;
#pragma unroll
        for (int ks = 0; ks < 8; ks++) {
#pragma unroll
            for (int ni = 0; ni < 8; ni++) {
                uint32_t b0 = Khb[(ni * 8 + lg) * KV_U + ks * 8 + lt];
                uint32_t b1 = Khb[(ni * 8 + lg) * KV_U + ks * 8 + 4 + lt];
                MMA_F16(s[ni][0], s[ni][1], s[ni][2], s[ni][3],
                        qf[ks][0], qf[ks][1], qf[ks][2], qf[ks][3], b0, b1);
            }
        }

        // scale + amask + causal NEG, row max
        float mx0 = -INFINITY, mx1 = -INFINITY;
#pragma unroll
        for (int ni = 0; ni < 8; ni++) {
            int col = ni * 8 + lt * 2;
            int key = kc + col;
            float v0 = s[ni][0] * 0.015625f + am0[ni].x;
            float v1 = s[ni][1] * 0.015625f + am0[ni].y;
            float v2 = s[ni][2] * 0.015625f + am1[ni].x;
            float v3 = s[ni][3] * 0.015625f + am1[ni].y;
            if (key     <= r0) v0 += NEGV;
            if (key + 1 <= r0) v1 += NEGV;
            if (key     <= r1) v2 += NEGV;
            if (key + 1 <= r1) v3 += NEGV;
            s[ni][0] = v0; s[ni][1] = v1; s[ni][2] = v2; s[ni][3] = v3;
            mx0 = fmaxf(mx0, fmaxf(v0, v1));
            mx1 = fmaxf(mx1, fmaxf(v2, v3));
        }
        mx0 = fmaxf(mx0, __shfl_xor_sync(0xffffffffu, mx0, 1));
        mx0 = fmaxf(mx0, __shfl_xor_sync(0xffffffffu, mx0, 2));
        mx1 = fmaxf(mx1, __shfl_xor_sync(0xffffffffu, mx1, 1));
        mx1 = fmaxf(mx1, __shfl_xor_sync(0xffffffffu, mx1, 2));

        float nm0 = fmaxf(m0, mx0), nm1 = fmaxf(m1, mx1);
        float corr0 = __expf(m0 - nm0), corr1 = __expf(m1 - nm1);
        float ls0 = 0.0f, ls1 = 0.0f;
        uint32_t pp[8][2];   // P packed: [ni][0]=rows lg h2(p0,p1), [1]=rows lg+8
#pragma unroll
        for (int ni = 0; ni < 8; ni++) {
            float p0 = __expf(s[ni][0] - nm0);
            float p1 = __expf(s[ni][1] - nm0);
            float p2 = __expf(s[ni][2] - nm1);
            float p3 = __expf(s[ni][3] - nm1);
            ls0 += p0 + p1;
            ls1 += p2 + p3;
            __half2 h01 = __floats2half2_rn(p0, p1);
            __half2 h23 = __floats2half2_rn(p2, p3);
            pp[ni][0] = *(uint32_t*)&h01;
            pp[ni][1] = *(uint32_t*)&h23;
        }
        ls0 += __shfl_xor_sync(0xffffffffu, ls0, 1);
        ls0 += __shfl_xor_sync(0xffffffffu, ls0, 2);
        ls1 += __shfl_xor_sync(0xffffffffu, ls1, 1);
        ls1 += __shfl_xor_sync(0xffffffffu, ls1, 2);
        l0 = l0 * corr0 + ls0;
        l1 = l1 * corr1 + ls1;
        m0 = nm0; m1 = nm1;
#pragma unroll
        for (int ni = 0; ni < 16; ni++) {
            o[ni][0] *= corr0; o[ni][1] *= corr0;
            o[ni][2] *= corr1; o[ni][3] *= corr1;
        }

        // O += P @ V : A-fragments come straight from registers
        // (a0,a1,a2,a3) for k-step ks = (pp[2ks][0], pp[2ks][1],
        //                                pp[2ks+1][0], pp[2ks+1][1])
#pragma unroll
        for (int ks = 0; ks < 4; ks++) {
            uint32_t a0 = pp[2 * ks][0];
            uint32_t a1 = pp[2 * ks][1];
            uint32_t a2 = pp[2 * ks + 1][0];
            uint32_t a3 = pp[2 * ks + 1][1];
#pragma unroll
            for (int nj = 0; nj < 8; nj++) {
                uint32_t b0, b1, b2, b3;
                LDSM_X4_T(b0, b1, b2, b3,
                          vBase + (ks * 16) * KV_STRIDE + nj * 32);
                MMA_F16(o[nj * 2][0], o[nj * 2][1], o[nj * 2][2], o[nj * 2][3],
                        a0, a1, a2, a3, b0, b1);
                MMA_F16(o[nj * 2 + 1][0], o[nj * 2 + 1][1],
                        o[nj * 2 + 1][2], o[nj * 2 + 1][3],
                        a0, a1, a2, a3, b2, b3);
            }
        }

        // this warp is done reading stage stg
        __syncwarp();
        if (lane == 0)
            MBAR_ARRIVE(smb + A_EMPTY + stg * 8);

        if (kc + ANS * AKC < S) {
            if (lane == 0)
                mbar_wait(smb + A_EMPTY + stg * 8, fpar);
            issue(kc + ANS * AKC, stg);
        }
    }

    // epilogue: /l, fp16 out
    float inv0 = 1.0f / l0, inv1 = 1.0f / l1;
#pragma unroll
    for (int ni = 0; ni < 16; ni++) {
        int col = ni * 8 + lt * 2;
        __half2 w0 = __floats2half2_rn(o[ni][0] * inv0, o[ni][1] * inv0);
        __half2 w1 = __floats2half2_rn(o[ni][2] * inv1, o[ni][3] * inv1);
        *(__half2*)(O + (size_t)r0 * D + h0 + col) = w0;
        *(__half2*)(O + (size_t)r1 * D + h0 + col) = w1;
    }
}

// ---------------------------------------------------------------------------
extern "C" void kernel_launch(void* const* d_in, const int* in_sizes, int n_in,
                              void* d_out, int out_size)
{
    const float* hidden = (const float*)d_in[0];
    const float* amask  = (const float*)d_in[1];
    const float* cosp   = (const float*)d_in[2];
    const float* sinp   = (const float*)d_in[3];
    const float* wq     = (const float*)d_in[4];
    const float* wk     = (const float*)d_in[5];
    const float* wv     = (const float*)d_in[6];
    const float* wo     = (const float*)d_in[7];
    float* out = (float*)d_out;

    __half *hh, *wth, *qh, *kh, *vh, *aoh;
    cudaGetSymbolAddress((void**)&hh,  g_hh);
    cudaGetSymbolAddress((void**)&wth, g_wth);
    cudaGetSymbolAddress((void**)&qh,  g_qh);
    cudaGetSymbolAddress((void**)&kh,  g_kh);
    cudaGetSymbolAddress((void**)&vh,  g_vh);
    cudaGetSymbolAddress((void**)&aoh, g_aoh);

    cudaFuncSetAttribute(attn_kernel,
                         cudaFuncAttributeMaxDynamicSharedMemorySize, ATTN_SMEM);
    cudaFuncSetAttribute(hgemm_kernel<1>,
                         cudaFuncAttributeMaxDynamicSharedMemorySize, GEMM_SMEM);
    cudaFuncSetAttribute(hgemm_kernel<0>,
                         cudaFuncAttributeMaxDynamicSharedMemorySize, GEMM_SMEM);

    prep_kernel<<<dim3(16384, 1, 5), 256>>>(hidden, wq, wk, wv, wo, hh, wth);

    hgemm_kernel<1><<<dim3(3 * (D / GBN), S / GBM), 256, GEMM_SMEM>>>(
        hh, wth, (size_t)D * D, 3, qh, kh, vh);

    rope_h_kernel<<<dim3((S * D / 4) / 256, 2), 256>>>(qh, kh, cosp, sinp);

    attn_kernel<<<dim3(S / AQB, H), 256, ATTN_SMEM>>>(qh, kh, vh, amask, aoh);

    hgemm_kernel<0><<<dim3(D / GBN, S / GBM), 256, GEMM_SMEM>>>(
        aoh, wth + 3 * (size_t)D * D, 0, 1, out, out, out);
}